// round 13
// baseline (speedup 1.0000x reference)
#include <cuda_runtime.h>
#include <cuda_fp16.h>
#include <cstdint>

// out = x @ kernel[2]  (seq_len==1 -> softmax over length-1 axis is identity)
// x: [8192,1024] f32, kernel: [3,1024,1024] f32, out: [8192,1024] f32
#define BROWS 8192
#define DDIM  1024

__device__ __half g_xh[BROWS * DDIM];   // 16 MB
__device__ __half g_wh[DDIM * DDIM];    // 2 MB, [K,N] row-major
__device__ int    g_cvt_ctr;            // convert chunk ticket counter
__device__ int    g_tile_ctr;           // GEMM tile ticket counter
__device__ int    g_done[16];           // per-k-tile convert completion counters

#define CH_PER_KT 20                    // 16 x-chunks + 4 w-chunks per k-tile
#define N_CVT     (16 * CH_PER_KT)      // 320 convert tickets

// ------------------------- PTX helpers -------------------------
static __device__ __forceinline__ uint32_t smem_u32(const void* p) {
    uint32_t a;
    asm("{ .reg .u64 t; cvta.to.shared.u64 t, %1; cvt.u32.u64 %0, t; }" : "=r"(a) : "l"(p));
    return a;
}
static __device__ __forceinline__ void cpa16(uint32_t saddr, const void* gptr) {
    asm volatile("cp.async.cg.shared.global [%0], [%1], 16;" :: "r"(saddr), "l"(gptr));
}
static __device__ __forceinline__ void cp_commit() {
    asm volatile("cp.async.commit_group;" ::: "memory");
}
static __device__ __forceinline__ void cp_wait2() {
    asm volatile("cp.async.wait_group 2;" ::: "memory");
}
static __device__ __forceinline__ void cp_wait0() {
    asm volatile("cp.async.wait_group 0;" ::: "memory");
}
static __device__ __forceinline__ void ldsm4(uint32_t* r, uint32_t a) {
    asm volatile("ldmatrix.sync.aligned.m8n8.x4.shared.b16 {%0,%1,%2,%3}, [%4];"
                 : "=r"(r[0]), "=r"(r[1]), "=r"(r[2]), "=r"(r[3]) : "r"(a));
}
static __device__ __forceinline__ void ldsm4t(uint32_t* r, uint32_t a) {
    asm volatile("ldmatrix.sync.aligned.m8n8.x4.trans.shared.b16 {%0,%1,%2,%3}, [%4];"
                 : "=r"(r[0]), "=r"(r[1]), "=r"(r[2]), "=r"(r[3]) : "r"(a));
}
static __device__ __forceinline__ void mma16816(float* c, const uint32_t* a, const uint32_t* b) {
    asm volatile(
        "mma.sync.aligned.m16n8k16.row.col.f32.f16.f16.f32 "
        "{%0,%1,%2,%3}, {%4,%5,%6,%7}, {%8,%9}, {%0,%1,%2,%3};"
        : "+f"(c[0]), "+f"(c[1]), "+f"(c[2]), "+f"(c[3])
        : "r"(a[0]), "r"(a[1]), "r"(a[2]), "r"(a[3]), "r"(b[0]), "r"(b[1]));
}

// ------------------------- reset kernel -------------------------
__global__ void reset_kernel() {
    if (threadIdx.x == 0) {
        g_cvt_ctr = 0;
        g_tile_ctr = 0;
    }
    if (threadIdx.x < 16) g_done[threadIdx.x] = 0;
}

// ------------------------- fused convert + persistent GEMM ----------
// Phase 1: ticket-driven fp32->fp16 convert, k-tile-major order, per-kt done flags.
// Phase 2: R10 GEMM — 1024 tiles (BM=128 x BN=64), BK=64, 2 CTAs/SM,
// 256 threads = 8 warps (4x2), warp tile 32x32, 4-stage cp.async ring streaming
// across tile boundaries, dynamic tile tickets. load_step spins on done[kt].
#define ST_B_OFF    16384
#define STAGE_BYTES 24576
#define N_STAGES    4
#define CTRL_OFF    (N_STAGES * STAGE_BYTES)
#define GEMM_SMEM   (CTRL_OFF + 128)            // 98432
#define N_TILES     1024                         // 64 (M) x 16 (N)

__global__ void __launch_bounds__(256, 2) fused_kernel(const float4* __restrict__ x4,
                                                       const float4* __restrict__ w4,
                                                       float* __restrict__ out) {
    extern __shared__ char smem[];
    const uint32_t sb = smem_u32(smem);
    int* ticket_sm = (int*)(smem + CTRL_OFF);
    const int tid    = threadIdx.x;
    const int lane   = tid & 31;
    const int wid    = tid >> 5;
    const int warp_m = wid >> 1;   // 0..3 -> m offset *32
    const int warp_n = wid & 1;    // 0..1 -> n offset *32

    // =================== Phase 1: convert ===================
    // Ticket t: kt = t/20, sub = t%20. sub<16: x rows [sub*512, +512) x f4-cols
    // [kt*16, +16). sub>=16: w rows [kt*64+(sub-16)*16, +16) x all cols.
    for (;;) {
        if (tid == 0) ticket_sm[1] = atomicAdd(&g_cvt_ctr, 1);
        __syncthreads();
        int t = ticket_sm[1];
        __syncthreads();
        if (t >= N_CVT) break;
        int kt = t / CH_PER_KT, sub = t % CH_PER_KT;
        if (sub < 16) {
            uint2* dst = (uint2*)g_xh;
#pragma unroll 1
            for (int i = 0; i < 32; i += 4) {
                float4 v[4];
#pragma unroll
                for (int j = 0; j < 4; j++) {
                    int e = (i + j) * 256 + tid;                 // 0..8191
                    int r = sub * 512 + (e >> 4), cc = e & 15;
                    v[j] = x4[(size_t)r * 256 + kt * 16 + cc];
                }
#pragma unroll
                for (int j = 0; j < 4; j++) {
                    int e = (i + j) * 256 + tid;
                    int r = sub * 512 + (e >> 4), cc = e & 15;
                    __half2 lo = __floats2half2_rn(v[j].x, v[j].y);
                    __half2 hi = __floats2half2_rn(v[j].z, v[j].w);
                    dst[(size_t)r * 256 + kt * 16 + cc] =
                        make_uint2(*(uint32_t*)&lo, *(uint32_t*)&hi);
                }
            }
        } else {
            // 16 w rows x 256 f4 = 4096 f4
            int r0 = kt * 64 + (sub - 16) * 16;
            uint2* dst = (uint2*)g_wh;
#pragma unroll 1
            for (int i = 0; i < 16; i += 4) {
                float4 v[4];
#pragma unroll
                for (int j = 0; j < 4; j++) {
                    int e = (i + j) * 256 + tid;                 // 0..4095
                    v[j] = w4[(size_t)r0 * 256 + e];
                }
#pragma unroll
                for (int j = 0; j < 4; j++) {
                    int e = (i + j) * 256 + tid;
                    __half2 lo = __floats2half2_rn(v[j].x, v[j].y);
                    __half2 hi = __floats2half2_rn(v[j].z, v[j].w);
                    dst[(size_t)r0 * 256 + e] = make_uint2(*(uint32_t*)&lo, *(uint32_t*)&hi);
                }
            }
        }
        __syncthreads();
        if (tid == 0) {
            __threadfence();
            atomicAdd(&g_done[kt], 1);
        }
    }

    // =================== Phase 2: GEMM (R10) ===================
    // Per-thread load geometry (constants across all steps).
    int a_goff[4];
    uint32_t a_soff[4];
#pragma unroll
    for (int i = 0; i < 4; i++) {
        int ch = tid + i * 256, r = ch >> 3, c = ch & 7;
        a_goff[i] = r * DDIM + c * 8;
        a_soff[i] = r * 128 + ((c ^ (r & 7)) * 16);
    }
    int b_goff[2];
    uint32_t b_soff[2];
#pragma unroll
    for (int i = 0; i < 2; i++) {
        int ch = tid + i * 256, k = ch >> 3, c = ch & 7;
        b_goff[i] = k * DDIM + c * 8;
        b_soff[i] = ST_B_OFF + k * 128 + ((c ^ (k & 7)) * 16);
    }

    auto load_step = [&](int by, int bx, int kt, int s) {
        // Readiness gate: one volatile load in steady state.
        if (*(volatile int*)&g_done[kt] < CH_PER_KT) {
            while (*(volatile int*)&g_done[kt] < CH_PER_KT) {}
            __threadfence();
        }
        uint32_t st = sb + s * STAGE_BYTES;
#pragma unroll
        for (int i = 0; i < 4; i++)
            cpa16(st + a_soff[i], g_xh + (size_t)by * (128 * DDIM) + kt * 64 + a_goff[i]);
#pragma unroll
        for (int i = 0; i < 2; i++)
            cpa16(st + b_soff[i], g_wh + (size_t)kt * (64 * DDIM) + bx * 64 + b_goff[i]);
    };

    // First ticket.
    if (tid == 0) ticket_sm[0] = atomicAdd(&g_tile_ctr, 1);
    __syncthreads();
    int cur = ticket_sm[0];
    if (cur >= N_TILES) { cp_wait0(); return; }
    int cur_by = cur >> 4, cur_bx = cur & 15;

    float c[2][4][4];
#pragma unroll
    for (int i = 0; i < 2; i++)
#pragma unroll
        for (int j = 0; j < 4; j++)
#pragma unroll
            for (int q = 0; q < 4; q++) c[i][j][q] = 0.0f;

    // Prologue: steps 0..2 of first tile into stages 0..2.
#pragma unroll
    for (int p = 0; p < 3; p++) {
        load_step(cur_by, cur_bx, p, p);
        cp_commit();
    }

    int cs = 0;   // compute stage
    int ls = 3;   // load stage
    for (;;) {
        int nxt = N_TILES, nxt_by = 0, nxt_bx = 0;
        for (int kt = 0; kt < 16; kt++) {
            cp_wait2();
            __syncthreads();
            if (kt == 0 && tid == 0) ticket_sm[0] = atomicAdd(&g_tile_ctr, 1);
            if (kt == 12) {
                nxt = ticket_sm[0];       // written at kt==0, 12 barriers ago
                nxt_by = nxt >> 4;
                nxt_bx = nxt & 15;
            }
            // Load step kt+3 (of cur, or first steps of nxt); always commit one group.
            int lkt = kt + 3;
            if (lkt < 16)            load_step(cur_by, cur_bx, lkt, ls);
            else if (nxt < N_TILES)  load_step(nxt_by, nxt_bx, lkt - 16, ls);
            cp_commit();
            ls = (ls + 1) & 3;

            uint32_t st = sb + cs * STAGE_BYTES;
            cs = (cs + 1) & 3;
#pragma unroll
            for (int kk = 0; kk < 4; kk++) {
                uint32_t a[2][4], b[2][4];
#pragma unroll
                for (int mt = 0; mt < 2; mt++) {
                    int row = warp_m * 32 + mt * 16 + (lane & 15);
                    int ch  = kk * 2 + (lane >> 4);
                    ldsm4(a[mt], st + row * 128 + ((ch ^ (row & 7)) * 16));
                }
#pragma unroll
                for (int nt = 0; nt < 2; nt++) {
                    int k  = kk * 16 + (lane & 15);
                    int nc = warp_n * 4 + nt * 2 + (lane >> 4);
                    ldsm4t(b[nt], st + ST_B_OFF + k * 128 + ((nc ^ (k & 7)) * 16));
                }
#pragma unroll
                for (int mt = 0; mt < 2; mt++)
#pragma unroll
                    for (int nj = 0; nj < 4; nj++)
                        mma16816(c[mt][nj], a[mt], &b[nj >> 1][(nj & 1) * 2]);
            }
        }

        // Tile done: store (fire-and-forget, overlaps next tile's MMAs) + reset.
        {
            int cta_m = cur_by * 128;
            int cta_n = cur_bx * 64;
#pragma unroll
            for (int mt = 0; mt < 2; mt++) {
#pragma unroll
                for (int nj = 0; nj < 4; nj++) {
                    int row = cta_m + warp_m * 32 + mt * 16 + (lane >> 2);
                    int col = cta_n + warp_n * 32 + nj * 8 + (lane & 3) * 2;
                    *reinterpret_cast<float2*>(&out[(size_t)row * DDIM + col]) =
                        make_float2(c[mt][nj][0], c[mt][nj][1]);
                    *reinterpret_cast<float2*>(&out[(size_t)(row + 8) * DDIM + col]) =
                        make_float2(c[mt][nj][2], c[mt][nj][3]);
                    c[mt][nj][0] = 0.0f; c[mt][nj][1] = 0.0f;
                    c[mt][nj][2] = 0.0f; c[mt][nj][3] = 0.0f;
                }
            }
        }

        cur = nxt;
        if (cur >= N_TILES) break;
        cur_by = nxt_by;
        cur_bx = nxt_bx;
    }
    cp_wait0();  // drain trailing groups before exit
}

// ------------------------- launch -------------------------
extern "C" void kernel_launch(void* const* d_in, const int* in_sizes, int n_in,
                              void* d_out, int out_size) {
    const float* x = (const float*)d_in[0];                 // [8192,1024]
    const float* kern = (const float*)d_in[1];              // [3,1024,1024]
    const float* wv = kern + 2L * DDIM * DDIM;              // kernel[2]: [K,N]
    float* out = (float*)d_out;

    reset_kernel<<<1, 32>>>();

    int dev = 0, nsm = 148;
    cudaGetDevice(&dev);
    cudaDeviceGetAttribute(&nsm, cudaDevAttrMultiProcessorCount, dev);
    int grid = 2 * nsm;
    if (grid < 1 || grid > N_TILES) grid = 296;

    cudaFuncSetAttribute(fused_kernel,
                         cudaFuncAttributeMaxDynamicSharedMemorySize, GEMM_SMEM);
    fused_kernel<<<grid, 256, GEMM_SMEM>>>((const float4*)x, (const float4*)wv, out);
}

// round 14
// speedup vs baseline: 1.1880x; 1.1880x over previous
#include <cuda_runtime.h>
#include <cuda_fp16.h>
#include <cstdint>

// out = x @ kernel[2]  (seq_len==1 -> softmax over length-1 axis is identity)
// x: [8192,1024] f32, kernel: [3,1024,1024] f32, out: [8192,1024] f32
#define BROWS 8192
#define DDIM  1024

__device__ __half g_xh[BROWS * DDIM];   // 16 MB
__device__ __half g_wh[DDIM * DDIM];    // 2 MB, [K,N] row-major
__device__ int    g_ctr;                // dynamic tile ticket counter

// ------------------------- PTX helpers -------------------------
static __device__ __forceinline__ uint32_t smem_u32(const void* p) {
    uint32_t a;
    asm("{ .reg .u64 t; cvta.to.shared.u64 t, %1; cvt.u32.u64 %0, t; }" : "=r"(a) : "l"(p));
    return a;
}
static __device__ __forceinline__ void cpa16(uint32_t saddr, const void* gptr) {
    asm volatile("cp.async.cg.shared.global [%0], [%1], 16;" :: "r"(saddr), "l"(gptr));
}
static __device__ __forceinline__ void cp_commit() {
    asm volatile("cp.async.commit_group;" ::: "memory");
}
static __device__ __forceinline__ void cp_wait0() {
    asm volatile("cp.async.wait_group 0;" ::: "memory");
}
static __device__ __forceinline__ void ldsm4(uint32_t* r, uint32_t a) {
    asm volatile("ldmatrix.sync.aligned.m8n8.x4.shared.b16 {%0,%1,%2,%3}, [%4];"
                 : "=r"(r[0]), "=r"(r[1]), "=r"(r[2]), "=r"(r[3]) : "r"(a));
}
static __device__ __forceinline__ void ldsm4t(uint32_t* r, uint32_t a) {
    asm volatile("ldmatrix.sync.aligned.m8n8.x4.trans.shared.b16 {%0,%1,%2,%3}, [%4];"
                 : "=r"(r[0]), "=r"(r[1]), "=r"(r[2]), "=r"(r[3]) : "r"(a));
}
static __device__ __forceinline__ void mma16816(float* c, const uint32_t* a, const uint32_t* b) {
    asm volatile(
        "mma.sync.aligned.m16n8k16.row.col.f32.f16.f16.f32 "
        "{%0,%1,%2,%3}, {%4,%5,%6,%7}, {%8,%9}, {%0,%1,%2,%3};"
        : "+f"(c[0]), "+f"(c[1]), "+f"(c[2]), "+f"(c[3])
        : "r"(a[0]), "r"(a[1]), "r"(a[2]), "r"(a[3]), "r"(b[0]), "r"(b[1]));
}

// ------------------------- convert kernel (R10, unchanged) -------------------------
__global__ void __launch_bounds__(256) cvt_kernel(const float4* __restrict__ x,
                                                  const float4* __restrict__ w,
                                                  int nx4) {
    if (blockIdx.x == 0 && threadIdx.x == 0) g_ctr = 0;
    int base = blockIdx.x * 1024 + threadIdx.x;
    const float4* src;
    uint2* dst;
    if (base < nx4) {
        src = x;
        dst = (uint2*)g_xh;
    } else {
        src = w - nx4;
        dst = ((uint2*)g_wh) - nx4;
    }
    float4 v[4];
#pragma unroll
    for (int j = 0; j < 4; j++) v[j] = src[base + j * 256];
#pragma unroll
    for (int j = 0; j < 4; j++) {
        __half2 lo = __floats2half2_rn(v[j].x, v[j].y);
        __half2 hi = __floats2half2_rn(v[j].z, v[j].w);
        dst[base + j * 256] = make_uint2(*(uint32_t*)&lo, *(uint32_t*)&hi);
    }
}

// ------------------------- persistent dynamic GEMM, epoch pipeline ----------
// 1024 tiles (BM=128 x BN=64), BK=32/step, 32 steps/tile. 2 CTAs/SM,
// 256 threads = 8 warps (4x2), warp tile 32x32. 8 stages of 12KB
// (A 8KB [128 rows x 64B sw] | B 4KB [32 k-rows x 128B sw]); barrier epoch = 4
// steps: compute stages (u..u+3)&7 while loading (u+4..u+7)&7 (disjoint mod 8).
#define ST_B_OFF    8192
#define STAGE_BYTES 12288
#define N_STAGES    8
#define CTRL_OFF    (N_STAGES * STAGE_BYTES)            // 98304
#define GEMM_SMEM   (CTRL_OFF + 128)                    // 98432
#define N_TILES     1024                                 // 64 (M) x 16 (N)

__global__ void __launch_bounds__(256, 2) gemm_persist_kernel(float* __restrict__ out) {
    extern __shared__ char smem[];
    const uint32_t sb = smem_u32(smem);
    int* ticket_sm = (int*)(smem + CTRL_OFF);
    const int tid    = threadIdx.x;
    const int lane   = tid & 31;
    const int wid    = tid >> 5;
    const int warp_m = wid >> 1;   // 0..3 -> m offset *32
    const int warp_n = wid & 1;    // 0..1 -> n offset *32

    // Per-thread load geometry (constants across all steps).
    // A: 128 rows x 4 chunks (16B) = 512 chunks, 2/thread. 64B rows, swizzle
    // chunk c of row r at r*64 + ((c ^ ((r>>1)&3))*16).
    int a_goff[2];
    uint32_t a_soff[2];
#pragma unroll
    for (int i = 0; i < 2; i++) {
        int ch = tid + i * 256, r = ch >> 2, c = ch & 3;
        a_goff[i] = r * DDIM + c * 8;
        a_soff[i] = r * 64 + ((c ^ ((r >> 1) & 3)) * 16);
    }
    // B: 32 k-rows x 8 chunks = 256 chunks, 1/thread. 128B rows, classic swizzle.
    int b_goff;
    uint32_t b_soff;
    {
        int k = tid >> 3, c = tid & 7;
        b_goff = k * DDIM + c * 8;
        b_soff = ST_B_OFF + k * 128 + ((c ^ (k & 7)) * 16);
    }

    auto load_step = [&](int by, int bx, int kt, int s) {
        uint32_t st = sb + s * STAGE_BYTES;
#pragma unroll
        for (int i = 0; i < 2; i++)
            cpa16(st + a_soff[i], g_xh + (size_t)by * (128 * DDIM) + kt * 32 + a_goff[i]);
        cpa16(st + b_soff, g_wh + (size_t)kt * (32 * DDIM) + bx * 64 + b_goff);
    };

    // First ticket.
    if (tid == 0) ticket_sm[0] = atomicAdd(&g_ctr, 1);
    __syncthreads();
    int cur = ticket_sm[0];
    if (cur >= N_TILES) return;
    int cur_by = cur >> 4, cur_bx = cur & 15;

    float c[2][4][4];
#pragma unroll
    for (int i = 0; i < 2; i++)
#pragma unroll
        for (int j = 0; j < 4; j++)
#pragma unroll
            for (int q = 0; q < 4; q++) c[i][j][q] = 0.0f;

    // Prologue: steps 0..3 into stages 0..3 (one commit each).
#pragma unroll
    for (int p = 0; p < 4; p++) {
        load_step(cur_by, cur_bx, p, p);
        cp_commit();
    }

    for (;;) {
        int nxt = N_TILES, nxt_by = 0, nxt_bx = 0;
#pragma unroll 1
        for (int e = 0; e < 8; e++) {
            // Epoch start: all outstanding groups (steps 4e..4e+3) must be done.
            cp_wait0();
            __syncthreads();
            if (e == 0 && tid == 0) ticket_sm[0] = atomicAdd(&g_ctr, 1);
            if (e == 6) {
                nxt = ticket_sm[0];       // written at e==0, 6 barriers ago
                nxt_by = nxt >> 4;
                nxt_bx = nxt & 15;
            }

            // Issue the next 4 load-steps first (max prefetch), one group each.
#pragma unroll
            for (int i = 0; i < 4; i++) {
                int lu = e * 4 + 4 + i;          // steps u+4..u+7
                if (lu < 32)             load_step(cur_by, cur_bx, lu, lu & 7);
                else if (nxt < N_TILES)  load_step(nxt_by, nxt_bx, lu - 32, lu & 7);
                cp_commit();
            }

            // Compute steps u..u+3.
#pragma unroll
            for (int i = 0; i < 4; i++) {
                int u = e * 4 + i;
                uint32_t st = sb + (u & 7) * STAGE_BYTES;
#pragma unroll
                for (int kk = 0; kk < 2; kk++) {
                    uint32_t a[2][4], b[2][4];
#pragma unroll
                    for (int mt = 0; mt < 2; mt++) {
                        int row = warp_m * 32 + mt * 16 + (lane & 15);
                        int ch  = kk * 2 + (lane >> 4);
                        ldsm4(a[mt], st + row * 64 + ((ch ^ ((row >> 1) & 3)) * 16));
                    }
#pragma unroll
                    for (int nt = 0; nt < 2; nt++) {
                        int k  = kk * 16 + (lane & 15);
                        int nc = warp_n * 4 + nt * 2 + (lane >> 4);
                        ldsm4t(b[nt], st + ST_B_OFF + k * 128 + ((nc ^ (k & 7)) * 16));
                    }
#pragma unroll
                    for (int mt = 0; mt < 2; mt++)
#pragma unroll
                        for (int nj = 0; nj < 4; nj++)
                            mma16816(c[mt][nj], a[mt], &b[nj >> 1][(nj & 1) * 2]);
                }
            }
        }

        // Tile done: store (fire-and-forget, overlaps next tile's loads) + reset.
        {
            int cta_m = cur_by * 128;
            int cta_n = cur_bx * 64;
#pragma unroll
            for (int mt = 0; mt < 2; mt++) {
#pragma unroll
                for (int nj = 0; nj < 4; nj++) {
                    int row = cta_m + warp_m * 32 + mt * 16 + (lane >> 2);
                    int col = cta_n + warp_n * 32 + nj * 8 + (lane & 3) * 2;
                    *reinterpret_cast<float2*>(&out[(size_t)row * DDIM + col]) =
                        make_float2(c[mt][nj][0], c[mt][nj][1]);
                    *reinterpret_cast<float2*>(&out[(size_t)(row + 8) * DDIM + col]) =
                        make_float2(c[mt][nj][2], c[mt][nj][3]);
                    c[mt][nj][0] = 0.0f; c[mt][nj][1] = 0.0f;
                    c[mt][nj][2] = 0.0f; c[mt][nj][3] = 0.0f;
                }
            }
        }

        cur = nxt;
        if (cur >= N_TILES) break;
        cur_by = nxt_by;
        cur_bx = nxt_bx;
    }
    cp_wait0();  // drain trailing groups before exit
}

// ------------------------- launch -------------------------
extern "C" void kernel_launch(void* const* d_in, const int* in_sizes, int n_in,
                              void* d_out, int out_size) {
    const float* x = (const float*)d_in[0];                 // [8192,1024]
    const float* kern = (const float*)d_in[1];              // [3,1024,1024]
    const float* wv = kern + 2L * DDIM * DDIM;              // kernel[2]: [K,N]
    float* out = (float*)d_out;

    const int nx4 = BROWS * DDIM / 4;   // 2,097,152
    const int nw4 = DDIM * DDIM / 4;    // 262,144
    cvt_kernel<<<(nx4 + nw4) / 1024, 256>>>((const float4*)x, (const float4*)wv, nx4);

    int dev = 0, nsm = 148;
    cudaGetDevice(&dev);
    cudaDeviceGetAttribute(&nsm, cudaDevAttrMultiProcessorCount, dev);
    int grid = 2 * nsm;
    if (grid < 1 || grid > N_TILES) grid = 296;

    cudaFuncSetAttribute(gemm_persist_kernel,
                         cudaFuncAttributeMaxDynamicSharedMemorySize, GEMM_SMEM);
    gemm_persist_kernel<<<grid, 256, GEMM_SMEM>>>(out);
}

// round 15
// speedup vs baseline: 1.2568x; 1.0579x over previous
#include <cuda_runtime.h>
#include <cuda_fp16.h>
#include <cstdint>

// out = x @ kernel[2]  (seq_len==1 -> softmax over length-1 axis is identity)
// x: [8192,1024] f32, kernel: [3,1024,1024] f32, out: [8192,1024] f32
#define BROWS 8192
#define DDIM  1024

__device__ __half g_xh[BROWS * DDIM];   // 16 MB
__device__ __half g_wh[DDIM * DDIM];    // 2 MB, [K,N] row-major
__device__ int    g_ctr;                // dynamic tile ticket counter

// ------------------------- PTX helpers -------------------------
static __device__ __forceinline__ uint32_t smem_u32(const void* p) {
    uint32_t a;
    asm("{ .reg .u64 t; cvta.to.shared.u64 t, %1; cvt.u32.u64 %0, t; }" : "=r"(a) : "l"(p));
    return a;
}
static __device__ __forceinline__ void cpa16(uint32_t saddr, const void* gptr) {
    asm volatile("cp.async.cg.shared.global [%0], [%1], 16;" :: "r"(saddr), "l"(gptr));
}
static __device__ __forceinline__ void cp_commit() {
    asm volatile("cp.async.commit_group;" ::: "memory");
}
static __device__ __forceinline__ void cp_wait1() {
    asm volatile("cp.async.wait_group 1;" ::: "memory");
}
static __device__ __forceinline__ void cp_wait0() {
    asm volatile("cp.async.wait_group 0;" ::: "memory");
}
static __device__ __forceinline__ void ldsm4(uint32_t* r, uint32_t a) {
    asm volatile("ldmatrix.sync.aligned.m8n8.x4.shared.b16 {%0,%1,%2,%3}, [%4];"
                 : "=r"(r[0]), "=r"(r[1]), "=r"(r[2]), "=r"(r[3]) : "r"(a));
}
static __device__ __forceinline__ void ldsm4t(uint32_t* r, uint32_t a) {
    asm volatile("ldmatrix.sync.aligned.m8n8.x4.trans.shared.b16 {%0,%1,%2,%3}, [%4];"
                 : "=r"(r[0]), "=r"(r[1]), "=r"(r[2]), "=r"(r[3]) : "r"(a));
}
static __device__ __forceinline__ void mma16816(float* c, const uint32_t* a, const uint32_t* b) {
    asm volatile(
        "mma.sync.aligned.m16n8k16.row.col.f32.f16.f16.f32 "
        "{%0,%1,%2,%3}, {%4,%5,%6,%7}, {%8,%9}, {%0,%1,%2,%3};"
        : "+f"(c[0]), "+f"(c[1]), "+f"(c[2]), "+f"(c[3])
        : "r"(a[0]), "r"(a[1]), "r"(a[2]), "r"(a[3]), "r"(b[0]), "r"(b[1]));
}

// ------------------------- convert kernel (R10, unchanged) -------------------------
__global__ void __launch_bounds__(256) cvt_kernel(const float4* __restrict__ x,
                                                  const float4* __restrict__ w,
                                                  int nx4) {
    if (blockIdx.x == 0 && threadIdx.x == 0) g_ctr = 0;
    int base = blockIdx.x * 1024 + threadIdx.x;
    const float4* src;
    uint2* dst;
    if (base < nx4) {
        src = x;
        dst = (uint2*)g_xh;
    } else {
        src = w - nx4;
        dst = ((uint2*)g_wh) - nx4;
    }
    float4 v[4];
#pragma unroll
    for (int j = 0; j < 4; j++) v[j] = src[base + j * 256];
#pragma unroll
    for (int j = 0; j < 4; j++) {
        __half2 lo = __floats2half2_rn(v[j].x, v[j].y);
        __half2 hi = __floats2half2_rn(v[j].z, v[j].w);
        dst[base + j * 256] = make_uint2(*(uint32_t*)&lo, *(uint32_t*)&hi);
    }
}

// ------------------------- persistent dynamic GEMM, 4 CTAs/SM ----------
// 2048 tiles (BM=64 x BN=64), BK=64/step, 16 steps/tile. 4 CTAs/SM,
// 128 threads = 4 warps (2x2), warp tile 32x32. 3-stage cp.async ring
// streaming across tile boundaries; dynamic tile tickets.
// Stage: A 8KB [64 rows x 128B sw] | B 8KB [64 k-rows x 128B sw] = 16KB x 3.
#define ST_B_OFF    8192
#define STAGE_BYTES 16384
#define N_STAGES    3
#define CTRL_OFF    (N_STAGES * STAGE_BYTES)            // 49152
#define GEMM_SMEM   (CTRL_OFF + 128)                    // 49280
#define N_TILES     2048                                 // 128 (M) x 16 (N)

__global__ void __launch_bounds__(128, 4) gemm_persist_kernel(float* __restrict__ out) {
    extern __shared__ char smem[];
    const uint32_t sb = smem_u32(smem);
    int* ticket_sm = (int*)(smem + CTRL_OFF);
    const int tid    = threadIdx.x;
    const int lane   = tid & 31;
    const int wid    = tid >> 5;
    const int warp_m = wid >> 1;   // 0..1 -> m offset *32
    const int warp_n = wid & 1;    // 0..1 -> n offset *32

    // Per-thread load geometry (constants across all steps).
    // A: 64 rows x 8 chunks (16B) = 512 chunks, 4/thread.
    int a_goff[4];
    uint32_t a_soff[4];
#pragma unroll
    for (int i = 0; i < 4; i++) {
        int ch = tid + i * 128, r = ch >> 3, c = ch & 7;
        a_goff[i] = r * DDIM + c * 8;
        a_soff[i] = r * 128 + ((c ^ (r & 7)) * 16);
    }
    // B: 64 k-rows x 8 chunks = 512 chunks, 4/thread.
    int b_goff[4];
    uint32_t b_soff[4];
#pragma unroll
    for (int i = 0; i < 4; i++) {
        int ch = tid + i * 128, k = ch >> 3, c = ch & 7;
        b_goff[i] = k * DDIM + c * 8;
        b_soff[i] = ST_B_OFF + k * 128 + ((c ^ (k & 7)) * 16);
    }

    auto load_step = [&](int by, int bx, int kt, int s) {
        uint32_t st = sb + s * STAGE_BYTES;
#pragma unroll
        for (int i = 0; i < 4; i++)
            cpa16(st + a_soff[i], g_xh + (size_t)by * (64 * DDIM) + kt * 64 + a_goff[i]);
#pragma unroll
        for (int i = 0; i < 4; i++)
            cpa16(st + b_soff[i], g_wh + (size_t)kt * (64 * DDIM) + bx * 64 + b_goff[i]);
    };

    // First ticket.
    if (tid == 0) ticket_sm[0] = atomicAdd(&g_ctr, 1);
    __syncthreads();
    int cur = ticket_sm[0];
    if (cur >= N_TILES) return;
    int cur_by = cur >> 4, cur_bx = cur & 15;

    float c[2][4][4];
#pragma unroll
    for (int i = 0; i < 2; i++)
#pragma unroll
        for (int j = 0; j < 4; j++)
#pragma unroll
            for (int q = 0; q < 4; q++) c[i][j][q] = 0.0f;

    // Prologue: steps 0,1 of first tile into stages 0,1.
    load_step(cur_by, cur_bx, 0, 0);
    cp_commit();
    load_step(cur_by, cur_bx, 1, 1);
    cp_commit();

    int cs = 0;   // compute stage
    int ls = 2;   // load stage
    for (;;) {
        int nxt = N_TILES, nxt_by = 0, nxt_bx = 0;
        for (int kt = 0; kt < 16; kt++) {
            cp_wait1();
            __syncthreads();
            if (kt == 0 && tid == 0) ticket_sm[0] = atomicAdd(&g_ctr, 1);
            if (kt == 12) {
                nxt = ticket_sm[0];       // written at kt==0, 12 barriers ago
                nxt_by = nxt >> 4;
                nxt_bx = nxt & 15;
            }
            // Load step kt+2 (of cur, or first steps of nxt); always commit one group.
            int lkt = kt + 2;
            if (lkt < 16)            load_step(cur_by, cur_bx, lkt, ls);
            else if (nxt < N_TILES)  load_step(nxt_by, nxt_bx, lkt - 16, ls);
            cp_commit();
            ls = (ls + 1 == N_STAGES) ? 0 : ls + 1;

            uint32_t st = sb + cs * STAGE_BYTES;
            cs = (cs + 1 == N_STAGES) ? 0 : cs + 1;
#pragma unroll
            for (int kk = 0; kk < 4; kk++) {
                uint32_t a[2][4], b[2][4];
#pragma unroll
                for (int mt = 0; mt < 2; mt++) {
                    int row = warp_m * 32 + mt * 16 + (lane & 15);
                    int ch  = kk * 2 + (lane >> 4);
                    ldsm4(a[mt], st + row * 128 + ((ch ^ (row & 7)) * 16));
                }
#pragma unroll
                for (int nt = 0; nt < 2; nt++) {
                    int k  = kk * 16 + (lane & 15);
                    int nc = warp_n * 4 + nt * 2 + (lane >> 4);
                    ldsm4t(b[nt], st + ST_B_OFF + k * 128 + ((nc ^ (k & 7)) * 16));
                }
#pragma unroll
                for (int mt = 0; mt < 2; mt++)
#pragma unroll
                    for (int nj = 0; nj < 4; nj++)
                        mma16816(c[mt][nj], a[mt], &b[nj >> 1][(nj & 1) * 2]);
            }
        }

        // Tile done: store (fire-and-forget, overlaps next tile's MMAs) + reset.
        {
            int cta_m = cur_by * 64;
            int cta_n = cur_bx * 64;
#pragma unroll
            for (int mt = 0; mt < 2; mt++) {
#pragma unroll
                for (int nj = 0; nj < 4; nj++) {
                    int row = cta_m + warp_m * 32 + mt * 16 + (lane >> 2);
                    int col = cta_n + warp_n * 32 + nj * 8 + (lane & 3) * 2;
                    *reinterpret_cast<float2*>(&out[(size_t)row * DDIM + col]) =
                        make_float2(c[mt][nj][0], c[mt][nj][1]);
                    *reinterpret_cast<float2*>(&out[(size_t)(row + 8) * DDIM + col]) =
                        make_float2(c[mt][nj][2], c[mt][nj][3]);
                    c[mt][nj][0] = 0.0f; c[mt][nj][1] = 0.0f;
                    c[mt][nj][2] = 0.0f; c[mt][nj][3] = 0.0f;
                }
            }
        }

        cur = nxt;
        if (cur >= N_TILES) break;
        cur_by = nxt_by;
        cur_bx = nxt_bx;
    }
    cp_wait0();  // drain trailing groups before exit
}

// ------------------------- launch -------------------------
extern "C" void kernel_launch(void* const* d_in, const int* in_sizes, int n_in,
                              void* d_out, int out_size) {
    const float* x = (const float*)d_in[0];                 // [8192,1024]
    const float* kern = (const float*)d_in[1];              // [3,1024,1024]
    const float* wv = kern + 2L * DDIM * DDIM;              // kernel[2]: [K,N]
    float* out = (float*)d_out;

    const int nx4 = BROWS * DDIM / 4;   // 2,097,152
    const int nw4 = DDIM * DDIM / 4;    // 262,144
    cvt_kernel<<<(nx4 + nw4) / 1024, 256>>>((const float4*)x, (const float4*)wv, nx4);

    int dev = 0, nsm = 148;
    cudaGetDevice(&dev);
    cudaDeviceGetAttribute(&nsm, cudaDevAttrMultiProcessorCount, dev);
    int grid = 4 * nsm;
    if (grid < 1 || grid > N_TILES) grid = 592;

    cudaFuncSetAttribute(gemm_persist_kernel,
                         cudaFuncAttributeMaxDynamicSharedMemorySize, GEMM_SMEM);
    gemm_persist_kernel<<<grid, 128, GEMM_SMEM>>>(out);
}